// round 6
// baseline (speedup 1.0000x reference)
#include <cuda_runtime.h>
#include <math.h>

// Problem constants
#define BB     64
#define TT     2048
#define DD     40
#define HH     164
#define NOUT   7
#define JT     4               // hidden columns per CTA
#define NCOL   (HH / JT)       // 41 CTAs per layer
#define NLAYER 3
#define NCTA   (NCOL * NLAYER) // 123 CTAs (< 148 SMs -> co-resident)
#define TB     256             // 8 warps
#define KMAX   (HH + HH)       // 328
#define NCHUNK 4
#define RS     4               // h ring depth (4 slots -> consumer lag 3)

// ---- dynamic smem layout (bytes) ----
#define OFF_W   0
#define SZ_W    (KMAX * 16 * 8)            // splatted weights: 41984
#define OFF_X   (OFF_W + SZ_W)
#define SZ_X    (KMAX * BB * 4)            // staged [x;h]: 83968
#define OFF_P   (OFF_X + SZ_X)
#define SZ_P    (NCHUNK * 16 * BB * 4)     // k-split partials: 16384
#define OFF_C   (OFF_P + SZ_P)
#define SZ_C    (JT * BB * 4)
#define OFF_B   (OFF_C + SZ_C)
#define SZ_B    (16 * 4)
#define OFF_L   (OFF_B + SZ_B)
#define SZ_L    (BB * 4)
#define OFF_M   (OFF_L + SZ_L)             // mbarriers
#define SZ_M    (NCHUNK * 8)
#define SMEM_BYTES (OFF_M + SZ_M)          // ~140.4 KB

// ---------------- device scratch ----------------
__device__ __align__(256) float g_xT[TT * DD * BB];           // x transposed: [t][d][b]
__device__ __align__(256) float g_h[NLAYER * RS * HH * BB];   // h ring: [l][slot][j][b]
__device__ unsigned g_flag[NCTA * 32];                        // per-CTA phase flags, 128B apart

// ---------------- helpers ----------------
__device__ __forceinline__ unsigned long long fma2(unsigned long long a,
                                                   unsigned long long b,
                                                   unsigned long long c) {
    unsigned long long d;
    asm("fma.rn.f32x2 %0, %1, %2, %3;" : "=l"(d) : "l"(a), "l"(b), "l"(c));
    return d;
}
__device__ __forceinline__ unsigned long long splat2(float w) {
    unsigned long long v = (unsigned long long)__float_as_uint(w);
    return v | (v << 32);
}
__device__ __forceinline__ void bulk_g2s(void* dst_smem, const void* src, int bytes, unsigned mbar) {
    unsigned d = (unsigned)__cvta_generic_to_shared(dst_smem);
    asm volatile("cp.async.bulk.shared::cluster.global.mbarrier::complete_tx::bytes [%0], [%1], %2, [%3];"
                 :: "r"(d), "l"(src), "r"(bytes), "r"(mbar) : "memory");
}
__device__ __forceinline__ void mbar_init(unsigned addr, unsigned cnt) {
    asm volatile("mbarrier.init.shared.b64 [%0], %1;" :: "r"(addr), "r"(cnt) : "memory");
}
__device__ __forceinline__ void mbar_expect_tx(unsigned addr, unsigned bytes) {
    asm volatile("mbarrier.arrive.expect_tx.shared.b64 _, [%0], %1;" :: "r"(addr), "r"(bytes) : "memory");
}
__device__ __forceinline__ void mbar_wait(unsigned addr, unsigned parity) {
    asm volatile(
        "{\n\t"
        ".reg .pred P1;\n\t"
        "WAIT_%=:\n\t"
        "mbarrier.try_wait.parity.acquire.cta.shared::cta.b64 P1, [%0], %1, 0x989680;\n\t"
        "@P1 bra DONE_%=;\n\t"
        "bra WAIT_%=;\n\t"
        "DONE_%=:\n\t"
        "}"
        :: "r"(addr), "r"(parity) : "memory");
}
__device__ __forceinline__ unsigned flag_acq(const unsigned* p) {
    unsigned r;
    asm volatile("ld.global.acquire.gpu.u32 %0, [%1];" : "=r"(r) : "l"(p));
    return r;
}
__device__ __forceinline__ void flag_rel(unsigned* p, unsigned v) {
    asm volatile("st.global.release.gpu.u32 [%0], %1;" :: "l"(p), "r"(v) : "memory");
}

// ---------------- single persistent kernel ----------------
__global__ void __launch_bounds__(TB, 1) k_lstm(
    const float* __restrict__ x,
    const int*   __restrict__ lengths,
    const float* __restrict__ Wih0, const float* __restrict__ Whh0, const float* __restrict__ bb0,
    const float* __restrict__ Wih1, const float* __restrict__ Whh1, const float* __restrict__ bb1,
    const float* __restrict__ Wih2, const float* __restrict__ Whh2, const float* __restrict__ bb2,
    const float* __restrict__ fcw,  const float* __restrict__ fcb,
    float* __restrict__ out)
{
    extern __shared__ unsigned char smem[];
    unsigned long long* sW = (unsigned long long*)(smem + OFF_W);
    float* sX   = (float*)(smem + OFF_X);
    float* sP   = (float*)(smem + OFF_P);
    float* sC   = (float*)(smem + OFF_C);
    float* sB   = (float*)(smem + OFF_B);
    int*   sLen = (int*)  (smem + OFF_L);
    unsigned mb0 = (unsigned)__cvta_generic_to_shared(smem + OFF_M);

    const int tid = threadIdx.x;
    const int cta = blockIdx.x;
    const int l   = cta / NCOL;
    const int cb  = cta - l * NCOL;
    const int j0  = cb * JT;

    // Replay-safe phase base: flags all equal at launch (static 0 or prev final).
    const unsigned base = g_flag[cta * 32];

    const float *Wih, *Whh, *bias;
    int Din;
    if (l == 0)      { Wih = Wih0; Whh = Whh0; bias = bb0; Din = DD; }
    else if (l == 1) { Wih = Wih1; Whh = Whh1; bias = bb1; Din = HH; }
    else             { Wih = Wih2; Whh = Whh2; bias = bb2; Din = HH; }
    const int KTOT = Din + HH;
    const int Q    = (KTOT + NCHUNK - 1) / NCHUNK;

    // ---------- Phase A: weights->smem, zero g_h, transpose x ----------
    for (int idx = tid; idx < Din * 16; idx += TB) {
        int k = idx >> 4, r = idx & 15;
        int g = r >> 2, jj = r & 3;
        sW[k * 16 + r] = splat2(Wih[(g * HH + j0 + jj) * Din + k]);
    }
    for (int idx = tid; idx < HH * 16; idx += TB) {
        int k = idx >> 4, r = idx & 15;
        int g = r >> 2, jj = r & 3;
        sW[(Din + k) * 16 + r] = splat2(Whh[(g * HH + j0 + jj) * HH + k]);
    }
    if (tid < 16) {
        int g = tid >> 2, jj = tid & 3;
        sB[tid] = bias[g * HH + j0 + jj];
    }
    if (tid < BB) sLen[tid] = lengths[tid];
    if (tid < JT * BB) sC[tid] = 0.f;
    if (tid == 0) {
        #pragma unroll
        for (int c = 0; c < NCHUNK; ++c) mbar_init(mb0 + c * 8, 1);
    }
    // zero h ring (grid-strided)
    {
        const int NH = NLAYER * RS * HH * BB;
        for (int i = cta * TB + tid; i < NH; i += NCTA * TB) g_h[i] = 0.f;
    }
    // transpose x[B][T][D] -> g_xT[t][d][b], t strided over CTAs, staged via sX
    for (int t = cta; t < TT; t += NCTA) {
        __syncthreads();
        for (int idx = tid; idx < BB * DD; idx += TB) {
            int b = idx / DD, d = idx - b * DD;
            sX[idx] = x[(b * TT + t) * DD + d];
        }
        __syncthreads();
        for (int idx = tid; idx < BB * DD; idx += TB) {
            int d = idx >> 6, b = idx & 63;
            g_xT[t * DD * BB + idx] = sX[b * DD + d];
        }
    }
    __syncthreads();
    if (tid == 0) {
        asm volatile("fence.proxy.async;" ::: "memory");
        flag_rel(g_flag + cta * 32, base + 1);
    }
    if (tid < NCTA) {
        while (flag_acq(g_flag + tid * 32) < base + 1) __nanosleep(16);
    }
    __syncthreads();

    // ---------- poller config (per thread tid<NCTA) ----------
    // rel = owner_layer - l :  -1 (producer, lag 1), 0 (own, lag 1), +1 (consumer, lag 3), else skip
    int  pLag = 0;
    bool pAct = false;
    long long pOwnerMin = 0;
    if (tid < NCTA) {
        int lo  = tid / NCOL;
        int rel = lo - l;
        if (rel == -1 || rel == 0) { pLag = 1; pAct = true; }
        else if (rel == 1)         { pLag = 3; pAct = true; }
        pOwnerMin = (long long)base + 2 + lo;   // owner's first main-loop phase
    }

    const int lane = tid & 31;
    const int warp = tid >> 5;
    const int kg   = warp >> 1;
    const int r0   = (warp & 1) * 8 + (lane >> 4) * 4;
    const int b0i  = (lane & 15) * 4;
    const int kb   = kg * Q;

    // ---------- main loop: local steps u = 0..TT-1 ----------
    for (int u = 0; u < TT; ++u) {
        const unsigned myphase = base + 2 + (unsigned)(u + l);

        // elastic dependency wait (signed 64-bit: no underflow at small u)
        if (pAct) {
            long long req = (long long)base + 2 + (u + l) - pLag;
            if (req >= pOwnerMin) {              // else pre-satisfied by Phase-A flag
                unsigned required = (unsigned)req;
                while (flag_acq(g_flag + tid * 32) < required) __nanosleep(8);
            }
        }
        __syncthreads();

        const float* xin = (l == 0) ? (g_xT + u * DD * BB)
                                    : (g_h + ((l - 1) * RS + (u & (RS - 1))) * HH * BB);
        const float* hin = g_h + (l * RS + ((u + RS - 1) & (RS - 1))) * HH * BB;
        const unsigned par = (unsigned)(u & 1);

        // ---- elected thread issues all chunk copies (bulk async + mbarrier) ----
        if (tid == 0) {
            #pragma unroll
            for (int c = 0; c < NCHUNK; ++c) {
                int rb = c * Q;
                int re = min(rb + Q, KTOT);
                if (re <= rb) { mbar_expect_tx(mb0 + c * 8, 0); continue; }
                mbar_expect_tx(mb0 + c * 8, (unsigned)((re - rb) * BB * 4));
                int xr = min(Din, re) - rb;          // rows from xin
                if (xr > 0)
                    bulk_g2s(sX + rb * BB, xin + rb * BB, xr * BB * 4, mb0 + c * 8);
                int hrb = max(rb, Din) - Din;        // first h row
                int hre = re - Din;
                if (hre > hrb)
                    bulk_g2s(sX + (Din + hrb) * BB, hin + hrb * BB,
                             (hre - hrb) * BB * 4, mb0 + c * 8);
            }
        }

        // ---- wait only this warp's chunk, then GEMM over its k-range ----
        mbar_wait(mb0 + kg * 8, par);

        const int ke = min(kb + Q, KTOT);
        unsigned long long a0, a1, a2, a3, a4, a5, a6, a7;
        if (kg == 0) {
            a0 = a1 = splat2(sB[r0 + 0]);
            a2 = a3 = splat2(sB[r0 + 1]);
            a4 = a5 = splat2(sB[r0 + 2]);
            a6 = a7 = splat2(sB[r0 + 3]);
        } else {
            a0 = a1 = a2 = a3 = a4 = a5 = a6 = a7 = 0ull;
        }

        #pragma unroll 4
        for (int k = kb; k < ke; ++k) {
            ulonglong2 xv = *(const ulonglong2*)(sX + k * BB + b0i);
            ulonglong2 wA = *(const ulonglong2*)(sW + k * 16 + r0);
            ulonglong2 wB = *(const ulonglong2*)(sW + k * 16 + r0 + 2);
            a0 = fma2(xv.x, wA.x, a0);  a1 = fma2(xv.y, wA.x, a1);
            a2 = fma2(xv.x, wA.y, a2);  a3 = fma2(xv.y, wA.y, a3);
            a4 = fma2(xv.x, wB.x, a4);  a5 = fma2(xv.y, wB.x, a5);
            a6 = fma2(xv.x, wB.y, a6);  a7 = fma2(xv.y, wB.y, a7);
        }

        float* pp = sP + kg * (16 * BB);
        *(ulonglong2*)(pp + (r0 + 0) * BB + b0i) = make_ulonglong2(a0, a1);
        *(ulonglong2*)(pp + (r0 + 1) * BB + b0i) = make_ulonglong2(a2, a3);
        *(ulonglong2*)(pp + (r0 + 2) * BB + b0i) = make_ulonglong2(a4, a5);
        *(ulonglong2*)(pp + (r0 + 3) * BB + b0i) = make_ulonglong2(a6, a7);
        __syncthreads();

        // ---- elementwise + state update: 1 item/thread ----
        {
            float* hout = g_h + (l * RS + (u & (RS - 1))) * HH * BB;
            int b = tid & 63, jj = tid >> 6;
            float iv = 0.f, fv = 0.f, gv = 0.f, ov = 0.f;
            #pragma unroll
            for (int c = 0; c < NCHUNK; ++c) {
                const float* p = sP + c * (16 * BB);
                iv += p[(0  + jj) * BB + b];
                fv += p[(4  + jj) * BB + b];
                gv += p[(8  + jj) * BB + b];
                ov += p[(12 + jj) * BB + b];
            }
            float co = sC[jj * BB + b];
            float ig = 1.f / (1.f + expf(-iv));
            float fg = 1.f / (1.f + expf(-fv));
            float og = 1.f / (1.f + expf(-ov));
            float cn = fg * co + ig * tanhf(gv);
            float hn = og * tanhf(cn);
            bool  m  = (u < sLen[b]);
            int   j  = j0 + jj;
            float hpv = sX[(Din + j) * BB + b];   // frozen value if past length
            sC[jj * BB + b]  = m ? cn : co;
            hout[j * BB + b] = m ? hn : hpv;
        }
        __syncthreads();

        if (tid == 0) {
            asm volatile("fence.proxy.async;" ::: "memory");
            flag_rel(g_flag + cta * 32, myphase);
        }
    }

    // ---------- final FC on CTA 0 ----------
    if (cta == 0) {
        // wait all layer-2 CTAs to finish their last step (phase base+TT+3)
        if (tid >= 2 * NCOL && tid < NCTA) {
            const unsigned req = base + (unsigned)TT + 3;
            while (flag_acq(g_flag + tid * 32) < req) __nanosleep(16);
        }
        __syncthreads();
        const float* h2 = g_h + (2 * RS + ((TT - 1) & (RS - 1))) * HH * BB;
        for (int it = tid; it < BB * NOUT; it += TB) {
            int b = it / NOUT, o = it - b * NOUT;
            float acc = fcb[o];
            #pragma unroll 4
            for (int j = 0; j < HH; ++j)
                acc += __ldcv(h2 + j * BB + b) * fcw[o * HH + j];
            out[b * NOUT + o] = acc;
        }
        __syncthreads();
    }

    // align flags for next replay (uniform base)
    if (tid == 0) flag_rel(g_flag + cta * 32, base + (unsigned)TT + 8);
}

// ---------------- launch ----------------
extern "C" void kernel_launch(void* const* d_in, const int* in_sizes, int n_in,
                              void* d_out, int out_size) {
    const float* x       = (const float*)d_in[0];
    const int*   lengths = (const int*)  d_in[1];
    const float* Wih0    = (const float*)d_in[2];
    const float* Whh0    = (const float*)d_in[3];
    const float* b0      = (const float*)d_in[4];
    const float* Wih1    = (const float*)d_in[5];
    const float* Whh1    = (const float*)d_in[6];
    const float* b1      = (const float*)d_in[7];
    const float* Wih2    = (const float*)d_in[8];
    const float* Whh2    = (const float*)d_in[9];
    const float* b2      = (const float*)d_in[10];
    const float* fcw     = (const float*)d_in[11];
    const float* fcb     = (const float*)d_in[12];
    float* out = (float*)d_out;

    static bool attr_set = false;
    if (!attr_set) {
        cudaFuncSetAttribute(k_lstm, cudaFuncAttributeMaxDynamicSharedMemorySize, SMEM_BYTES);
        attr_set = true;
    }

    k_lstm<<<NCTA, TB, SMEM_BYTES>>>(x, lengths,
                                     Wih0, Whh0, b0,
                                     Wih1, Whh1, b1,
                                     Wih2, Whh2, b2,
                                     fcw, fcb, out);
}